// round 1
// baseline (speedup 1.0000x reference)
#include <cuda_runtime.h>
#include <math.h>

// Problem constants
namespace {
constexpr int kS = 2048;
constexpr int kB = 32;
constexpr int kD = 256;
constexpr int kH = 4;
constexpr int kN = kS * kB;   // 65536 rows
constexpr float kEps = 1e-5f;

// GEMM tiling
constexpr int BM = 128, BN = 128, BK = 16, TM = 8, TN = 8;
}  // namespace

// ---------------------------------------------------------------------------
// Scratch (device globals — no dynamic allocation allowed)
// ---------------------------------------------------------------------------
__device__ float g_bufq[2][(size_t)kN * kD];
__device__ float g_bufk[2][(size_t)kN * kD];
__device__ float g_bufv[2][(size_t)kN * kD];
__device__ float g_t2[(size_t)kN * kD];
__device__ float g_t4[(size_t)kN * kD];
__device__ double g_s1a[kD], g_s2a[kD], g_s1b[kD], g_s2b[kD];
__device__ float g_scA[kD], g_shA[kD], g_scB[kD], g_shB[kD];
__device__ float g_se[kB * kD], g_wv[kB * kD];
__device__ float g_concat[kB * kH * kD];

// ---------------------------------------------------------------------------
// Tiled SGEMM: C[m, n] = sum_d Aop[m, d] * W[n, d] + bias[n]
//   MODE 0: Aop = A
//   MODE 1: Aop = relu((A - A2) * sc[d] + sh[d])     (BN1 fused: A=k', A2=q')
//   MODE 2: Aop = relu(A * sc[d] + sh[d])            (BN2 fused)
// A is [kN, kD] row-major, W is [kD, kD] row-major, C is [kN, kD].
// ---------------------------------------------------------------------------
template <int MODE>
__global__ __launch_bounds__(256)
void gemm_kernel(const float* __restrict__ A, const float* __restrict__ A2,
                 const float* __restrict__ sc, const float* __restrict__ sh,
                 const float* __restrict__ W, const float* __restrict__ bias,
                 float* __restrict__ C) {
    __shared__ float As[BK][BM + 4];
    __shared__ float Bs[BK][BN + 4];

    const int tid = threadIdx.x;
    const int m0 = blockIdx.x * BM;
    const int n0 = blockIdx.y * BN;
    const int tx = tid & 15;         // 0..15 -> output cols
    const int ty = tid >> 4;         // 0..15 -> output rows
    const int lr = tid >> 2;         // loader row 0..63
    const int lc = (tid & 3) << 2;   // loader col {0,4,8,12}

    float acc[TM][TN];
#pragma unroll
    for (int i = 0; i < TM; i++)
#pragma unroll
        for (int j = 0; j < TN; j++) acc[i][j] = 0.f;

    for (int k0 = 0; k0 < kD; k0 += BK) {
        float4 s4, h4;
        if (MODE != 0) {
            s4 = *reinterpret_cast<const float4*>(&sc[k0 + lc]);
            h4 = *reinterpret_cast<const float4*>(&sh[k0 + lc]);
        }
#pragma unroll
        for (int rr = 0; rr < 2; rr++) {
            const int row = lr + rr * 64;
            // ---- A tile (with optional fused BN+ReLU transform) ----
            float4 a4 = *reinterpret_cast<const float4*>(
                &A[(size_t)(m0 + row) * kD + k0 + lc]);
            if (MODE == 1) {
                float4 q4 = *reinterpret_cast<const float4*>(
                    &A2[(size_t)(m0 + row) * kD + k0 + lc]);
                a4.x = fmaxf((a4.x - q4.x) * s4.x + h4.x, 0.f);
                a4.y = fmaxf((a4.y - q4.y) * s4.y + h4.y, 0.f);
                a4.z = fmaxf((a4.z - q4.z) * s4.z + h4.z, 0.f);
                a4.w = fmaxf((a4.w - q4.w) * s4.w + h4.w, 0.f);
            } else if (MODE == 2) {
                a4.x = fmaxf(a4.x * s4.x + h4.x, 0.f);
                a4.y = fmaxf(a4.y * s4.y + h4.y, 0.f);
                a4.z = fmaxf(a4.z * s4.z + h4.z, 0.f);
                a4.w = fmaxf(a4.w * s4.w + h4.w, 0.f);
            }
            As[lc + 0][row] = a4.x;
            As[lc + 1][row] = a4.y;
            As[lc + 2][row] = a4.z;
            As[lc + 3][row] = a4.w;

            // ---- B tile: Bs[k][j] = W[n0+j][k0+k] ----
            float4 b4 = *reinterpret_cast<const float4*>(
                &W[(size_t)(n0 + row) * kD + k0 + lc]);
            Bs[lc + 0][row] = b4.x;
            Bs[lc + 1][row] = b4.y;
            Bs[lc + 2][row] = b4.z;
            Bs[lc + 3][row] = b4.w;
        }
        __syncthreads();

#pragma unroll
        for (int kk = 0; kk < BK; kk++) {
            float af[TM], bf[TN];
            *reinterpret_cast<float4*>(&af[0]) =
                *reinterpret_cast<const float4*>(&As[kk][ty * TM]);
            *reinterpret_cast<float4*>(&af[4]) =
                *reinterpret_cast<const float4*>(&As[kk][ty * TM + 4]);
            *reinterpret_cast<float4*>(&bf[0]) =
                *reinterpret_cast<const float4*>(&Bs[kk][tx * TN]);
            *reinterpret_cast<float4*>(&bf[4]) =
                *reinterpret_cast<const float4*>(&Bs[kk][tx * TN + 4]);
#pragma unroll
            for (int i = 0; i < TM; i++)
#pragma unroll
                for (int j = 0; j < TN; j++) acc[i][j] += af[i] * bf[j];
        }
        __syncthreads();
    }

    // Epilogue: add bias, store
#pragma unroll
    for (int i = 0; i < TM; i++) {
        const int m = m0 + ty * TM + i;
#pragma unroll
        for (int j = 0; j < TN; j += 4) {
            const int n = n0 + tx * TN + j;
            float4 o;
            o.x = acc[i][j + 0] + bias[n + 0];
            o.y = acc[i][j + 1] + bias[n + 1];
            o.z = acc[i][j + 2] + bias[n + 2];
            o.w = acc[i][j + 3] + bias[n + 3];
            *reinterpret_cast<float4*>(&C[(size_t)m * kD + n]) = o;
        }
    }
}

// ---------------------------------------------------------------------------
// Per-channel sums for BatchNorm (double accumulation; x = X or X - Y)
// ---------------------------------------------------------------------------
__global__ void stats_kernel(const float* __restrict__ X,
                             const float* __restrict__ Y,
                             double* __restrict__ s1, double* __restrict__ s2) {
    const int d = threadIdx.x;
    double a = 0.0, q = 0.0;
    for (int r = blockIdx.x; r < kN; r += gridDim.x) {
        float x = X[(size_t)r * kD + d];
        if (Y) x -= Y[(size_t)r * kD + d];
        const double xx = (double)x;
        a += xx;
        q += xx * xx;
    }
    atomicAdd(&s1[d], a);
    atomicAdd(&s2[d], q);
}

// mean/var -> affine form: bn(x) = x * scale + shift
__global__ void bn_finalize_kernel(const double* __restrict__ s1,
                                   const double* __restrict__ s2,
                                   const float* __restrict__ gamma,
                                   const float* __restrict__ beta,
                                   float* __restrict__ scale,
                                   float* __restrict__ shift) {
    const int d = threadIdx.x;
    const double mean = s1[d] / (double)kN;
    const double var = s2[d] / (double)kN - mean * mean;
    const float rs = (float)rsqrt(var + (double)kEps);
    const float scv = rs * gamma[d];
    scale[d] = scv;
    shift[d] = beta[d] - (float)mean * scv;
}

// Zero per-head accumulators (grid = 32, block = 256 -> 8192 threads)
__global__ void zero_kernel(double* s1a, double* s2a, double* s1b, double* s2b,
                            float* se, float* wv) {
    const int g = blockIdx.x * blockDim.x + threadIdx.x;
    se[g] = 0.f;
    wv[g] = 0.f;
    if (g < kD) {
        s1a[g] = 0.0;
        s2a[g] = 0.0;
        s1b[g] = 0.0;
        s2b[g] = 0.0;
    }
}

// Softmax over s (no max-sub needed: |logits| <~ 4) fused with weighted V sum.
// grid = (kB, 16 s-chunks), block = 256 (one thread per d)
__global__ void softmax_accum_kernel(const float* __restrict__ T,
                                     const float* __restrict__ V,
                                     float* __restrict__ se,
                                     float* __restrict__ wv) {
    const int b = blockIdx.x;
    const int chunk = blockIdx.y;
    const int d = threadIdx.x;
    constexpr int kChunk = kS / 16;
    float pe = 0.f, pw = 0.f;
    for (int s = chunk * kChunk; s < (chunk + 1) * kChunk; s++) {
        const size_t idx = ((size_t)s * kB + b) * kD + d;
        const float e = expf(T[idx]);
        pe += e;
        pw += e * V[idx];
    }
    atomicAdd(&se[b * kD + d], pe);
    atomicAdd(&wv[b * kD + d], pw);
}

__global__ void softmax_final_kernel(const float* __restrict__ se,
                                     const float* __restrict__ wv,
                                     float* __restrict__ concat, int head) {
    const int b = blockIdx.x;
    const int d = threadIdx.x;
    concat[b * (kH * kD) + head * kD + d] = wv[b * kD + d] / se[b * kD + d];
}

// Final MLP: [B, H*D] -> relu -> [B,D] -> relu -> [B,D] -> out
__global__ __launch_bounds__(256)
void mlp_kernel(const float* __restrict__ concat,
                const float* __restrict__ mw0, const float* __restrict__ mb0,
                const float* __restrict__ mw1, const float* __restrict__ mb1,
                const float* __restrict__ mw2, const float* __restrict__ mb2,
                float* __restrict__ out) {
    __shared__ float xs[kH * kD];
    __shared__ float h0[kD];
    __shared__ float h1[kD];
    const int b = blockIdx.x;
    const int j = threadIdx.x;

    for (int t = j; t < kH * kD; t += kD) xs[t] = concat[b * kH * kD + t];
    __syncthreads();

    float acc = mb0[j];
    for (int t = 0; t < kH * kD; t++) acc += xs[t] * mw0[(size_t)j * (kH * kD) + t];
    h0[j] = fmaxf(acc, 0.f);
    __syncthreads();

    acc = mb1[j];
    for (int t = 0; t < kD; t++) acc += h0[t] * mw1[(size_t)j * kD + t];
    h1[j] = fmaxf(acc, 0.f);
    __syncthreads();

    acc = mb2[j];
    for (int t = 0; t < kD; t++) acc += h1[t] * mw2[(size_t)j * kD + t];
    out[b * kD + j] = acc;
}

// ---------------------------------------------------------------------------
// Launcher
// ---------------------------------------------------------------------------
extern "C" void kernel_launch(void* const* d_in, const int* in_sizes, int n_in,
                              void* d_out, int out_size) {
    (void)in_sizes; (void)n_in; (void)out_size;
    const float* in_q  = (const float*)d_in[0];
    const float* in_k  = (const float*)d_in[1];
    const float* in_v  = (const float*)d_in[2];
    const float* wq    = (const float*)d_in[3];
    const float* bqv   = (const float*)d_in[4];
    const float* wk    = (const float*)d_in[5];
    const float* bkv   = (const float*)d_in[6];
    const float* wvw   = (const float*)d_in[7];
    const float* bvv   = (const float*)d_in[8];
    const float* g1    = (const float*)d_in[9];
    const float* be1   = (const float*)d_in[10];
    const float* wl1   = (const float*)d_in[11];
    const float* bl1   = (const float*)d_in[12];
    const float* g2    = (const float*)d_in[13];
    const float* be2   = (const float*)d_in[14];
    const float* wl2   = (const float*)d_in[15];
    const float* bl2   = (const float*)d_in[16];
    const float* mw0   = (const float*)d_in[17];
    const float* mb0   = (const float*)d_in[18];
    const float* mw1   = (const float*)d_in[19];
    const float* mb1   = (const float*)d_in[20];
    const float* mw2   = (const float*)d_in[21];
    const float* mb2   = (const float*)d_in[22];

    float *bq, *bk, *bv, *t2, *t4, *scA, *shA, *scB, *shB, *se, *wv, *concat;
    double *s1a, *s2a, *s1b, *s2b;
    cudaGetSymbolAddress((void**)&bq, g_bufq);
    cudaGetSymbolAddress((void**)&bk, g_bufk);
    cudaGetSymbolAddress((void**)&bv, g_bufv);
    cudaGetSymbolAddress((void**)&t2, g_t2);
    cudaGetSymbolAddress((void**)&t4, g_t4);
    cudaGetSymbolAddress((void**)&s1a, g_s1a);
    cudaGetSymbolAddress((void**)&s2a, g_s2a);
    cudaGetSymbolAddress((void**)&s1b, g_s1b);
    cudaGetSymbolAddress((void**)&s2b, g_s2b);
    cudaGetSymbolAddress((void**)&scA, g_scA);
    cudaGetSymbolAddress((void**)&shA, g_shA);
    cudaGetSymbolAddress((void**)&scB, g_scB);
    cudaGetSymbolAddress((void**)&shB, g_shB);
    cudaGetSymbolAddress((void**)&se, g_se);
    cudaGetSymbolAddress((void**)&wv, g_wv);
    cudaGetSymbolAddress((void**)&concat, g_concat);

    const size_t bufElems = (size_t)kN * kD;
    const dim3 gemmGrid(kN / BM, kD / BN);

    const float *qin = in_q, *kin = in_k, *vin = in_v;
    for (int i = 0; i < kH; i++) {
        float* qout = bq + (size_t)(i & 1) * bufElems;
        float* kout = bk + (size_t)(i & 1) * bufElems;
        float* vout = bv + (size_t)(i & 1) * bufElems;

        zero_kernel<<<32, 256>>>(s1a, s2a, s1b, s2b, se, wv);

        gemm_kernel<0><<<gemmGrid, 256>>>(qin, nullptr, nullptr, nullptr,
                                          wq + (size_t)i * kD * kD, bqv + i * kD, qout);
        gemm_kernel<0><<<gemmGrid, 256>>>(kin, nullptr, nullptr, nullptr,
                                          wk + (size_t)i * kD * kD, bkv + i * kD, kout);
        gemm_kernel<0><<<gemmGrid, 256>>>(vin, nullptr, nullptr, nullptr,
                                          wvw + (size_t)i * kD * kD, bvv + i * kD, vout);

        stats_kernel<<<512, 256>>>(kout, qout, s1a, s2a);
        bn_finalize_kernel<<<1, 256>>>(s1a, s2a, g1 + i * kD, be1 + i * kD, scA, shA);

        gemm_kernel<1><<<gemmGrid, 256>>>(kout, qout, scA, shA,
                                          wl1 + (size_t)i * kD * kD, bl1 + i * kD, t2);

        stats_kernel<<<512, 256>>>(t2, nullptr, s1b, s2b);
        bn_finalize_kernel<<<1, 256>>>(s1b, s2b, g2 + i * kD, be2 + i * kD, scB, shB);

        gemm_kernel<2><<<gemmGrid, 256>>>(t2, nullptr, scB, shB,
                                          wl2 + (size_t)i * kD * kD, bl2 + i * kD, t4);

        softmax_accum_kernel<<<dim3(kB, 16), 256>>>(t4, vout, se, wv);
        softmax_final_kernel<<<kB, 256>>>(se, wv, concat, i);

        qin = qout; kin = kout; vin = vout;
    }

    mlp_kernel<<<kB, 256>>>(concat, mw0, mb0, mw1, mb1, mw2, mb2, (float*)d_out);
}

// round 3
// speedup vs baseline: 1.6622x; 1.6622x over previous
#include <cuda_runtime.h>
#include <cuda_bf16.h>
#include <math.h>
#include <stdint.h>

namespace {
constexpr int kS = 2048;
constexpr int kB = 32;
constexpr int kD = 256;
constexpr int kH = 4;
constexpr int kN = kS * kB;   // 65536 rows
constexpr float kEps = 1e-5f;
constexpr int kSmemStage = 65536;   // Ahi 16K | Alo 16K | Bhi 16K | Blo 16K
constexpr int kSmemTotal = 2 * kSmemStage;
}  // namespace

// ---------------------------------------------------------------------------
// Scratch (device globals — no dynamic allocation allowed)
// ---------------------------------------------------------------------------
__device__ float g_bufq[2][(size_t)kN * kD];
__device__ float g_bufk[2][(size_t)kN * kD];
__device__ float g_bufv[2][(size_t)kN * kD];
__device__ float g_t2[(size_t)kN * kD];
__device__ float g_t4[(size_t)kN * kD];
__device__ float g_s1a[kD], g_s2a[kD], g_s1b[kD], g_s2b[kD];
__device__ float g_scA[kD], g_shA[kD], g_scB[kD], g_shB[kD];
__device__ float g_se[kB * kD], g_wv[kB * kD];
__device__ float g_concat[kB * kH * kD];
// bf16 hi/lo weight images, swizzle baked into k position: 20 matrices
__device__ __nv_bfloat16 g_whi[20][kD * kD];
__device__ __nv_bfloat16 g_wlo[20][kD * kD];

// ---------------------------------------------------------------------------
// PTX helpers (all arch-generic: sm_80-level instructions only)
// ---------------------------------------------------------------------------
__device__ __forceinline__ uint32_t smem_u32(const void* p) {
    uint32_t a;
    asm("{ .reg .u64 t; cvta.to.shared.u64 t, %1; cvt.u32.u64 %0, t; }"
        : "=r"(a) : "l"(p));
    return a;
}

__device__ __forceinline__ void cp16(uint32_t dst, const void* src) {
    asm volatile("cp.async.cg.shared.global [%0], [%1], 16;"
                 :: "r"(dst), "l"(src));
}
#define CP_COMMIT() asm volatile("cp.async.commit_group;" ::: "memory")
#define CP_WAIT0()  asm volatile("cp.async.wait_group 0;" ::: "memory")

__device__ __forceinline__ void ldmx4(uint32_t* r, uint32_t addr) {
    asm volatile("ldmatrix.sync.aligned.m8n8.x4.shared.b16 {%0,%1,%2,%3}, [%4];"
                 : "=r"(r[0]), "=r"(r[1]), "=r"(r[2]), "=r"(r[3]) : "r"(addr));
}

__device__ __forceinline__ void mma16816(float* d, const uint32_t* a,
                                         uint32_t b0, uint32_t b1) {
    asm volatile(
        "mma.sync.aligned.m16n8k16.row.col.f32.bf16.bf16.f32 "
        "{%0,%1,%2,%3}, {%4,%5,%6,%7}, {%8,%9}, {%0,%1,%2,%3};"
        : "+f"(d[0]), "+f"(d[1]), "+f"(d[2]), "+f"(d[3])
        : "r"(a[0]), "r"(a[1]), "r"(a[2]), "r"(a[3]), "r"(b0), "r"(b1));
}

// ---------------------------------------------------------------------------
// Weight pre-conversion: fp32 W[n][k] -> bf16 hi/lo image with the 16B-granule
// XOR swizzle baked into the k position: k = c*64 + gg*8 + e is stored at
// k' = c*64 + (gg ^ (n & 7))*8 + e.
// ---------------------------------------------------------------------------
__global__ void preconvert_w(const float* __restrict__ wq, const float* __restrict__ wk,
                             const float* __restrict__ wv, const float* __restrict__ wl1,
                             const float* __restrict__ wl2) {
    const int g = blockIdx.x;  // 0..19 = slot*4 + head
    const int slot = g >> 2, head = g & 3;
    const float* src;
    switch (slot) {
        case 0: src = wq; break;
        case 1: src = wk; break;
        case 2: src = wv; break;
        case 3: src = wl1; break;
        default: src = wl2; break;
    }
    src += (size_t)head * kD * kD;

    const int idx = blockIdx.y * 256 + threadIdx.x;  // 0..4095 (grid.y = 16)
    const int n = idx >> 4;
    const int k0 = (idx & 15) * 16;
#pragma unroll
    for (int j = 0; j < 16; ++j) {
        const int k = k0 + j;
        const float x = src[n * kD + k];
        const __nv_bfloat16 h = __float2bfloat16(x);
        const __nv_bfloat16 l = __float2bfloat16(x - __bfloat162float(h));
        const int gg = (k >> 3) & 7;
        const int kpos = (k & ~63) | (((gg ^ (n & 7)) << 3)) | (k & 7);
        g_whi[g][n * kD + kpos] = h;
        g_wlo[g][n * kD + kpos] = l;
    }
}

// ---------------------------------------------------------------------------
// mma.sync GEMM: C[65536, 256] = Aop[65536, 256] @ W[256, 256]^T + bias
// bf16 hi/lo split, 3 terms, fp32 accumulate.
//   MODE 0: Aop = A
//   MODE 1: Aop = relu((A - A2) * sc + sh)
//   MODE 2: Aop = relu(A * sc + sh)
// Grid (512, 2), 256 threads. CTA tile 128x128; warp tile 64x32.
// ---------------------------------------------------------------------------
template <int MODE>
__global__ void __launch_bounds__(256, 1)
gemm_mma(const float* __restrict__ A, const float* __restrict__ A2,
         const float* __restrict__ sc, const float* __restrict__ sh,
         const __nv_bfloat16* __restrict__ Whi, const __nv_bfloat16* __restrict__ Wlo,
         const float* __restrict__ bias, float* __restrict__ C) {
    extern __shared__ __align__(1024) char smem[];
    const int tid = threadIdx.x;
    const int lane = tid & 31, warp = tid >> 5;
    const int wm = warp >> 2, wn = warp & 3;
    const int m0 = blockIdx.x * 128;
    const int n0 = blockIdx.y * 128;

    float acc[4][4][4];
#pragma unroll
    for (int i = 0; i < 4; ++i)
#pragma unroll
        for (int j = 0; j < 4; ++j)
#pragma unroll
            for (int e = 0; e < 4; ++e) acc[i][j][e] = 0.f;

    // --- A prefetch assignment: thread -> (row, 32-wide k half) ---
    const int ar = tid >> 1;
    const int ahalf = tid & 1;
    float va[32];

    auto ldgA = [&](int c) {
        const size_t base = (size_t)(m0 + ar) * kD + c * 64 + ahalf * 32;
        float4 t[8];
#pragma unroll
        for (int j = 0; j < 8; ++j) t[j] = *(const float4*)(A + base + j * 4);
        if (MODE == 1) {
#pragma unroll
            for (int j = 0; j < 8; ++j) {
                const float4 q = *(const float4*)(A2 + base + j * 4);
                t[j].x -= q.x; t[j].y -= q.y; t[j].z -= q.z; t[j].w -= q.w;
            }
        }
        if (MODE != 0) {
            const int kb = c * 64 + ahalf * 32;
#pragma unroll
            for (int j = 0; j < 8; ++j) {
                const float4 s4 = *(const float4*)(sc + kb + j * 4);
                const float4 h4 = *(const float4*)(sh + kb + j * 4);
                t[j].x = fmaxf(t[j].x * s4.x + h4.x, 0.f);
                t[j].y = fmaxf(t[j].y * s4.y + h4.y, 0.f);
                t[j].z = fmaxf(t[j].z * s4.z + h4.z, 0.f);
                t[j].w = fmaxf(t[j].w * s4.w + h4.w, 0.f);
            }
        }
#pragma unroll
        for (int j = 0; j < 8; ++j) {
            va[j * 4 + 0] = t[j].x; va[j * 4 + 1] = t[j].y;
            va[j * 4 + 2] = t[j].z; va[j * 4 + 3] = t[j].w;
        }
    };

    auto stsA = [&](int s) {
        char* ahp = smem + s * kSmemStage;
        char* alp = ahp + 16384;
#pragma unroll
        for (int jg = 0; jg < 4; ++jg) {
            union { __nv_bfloat16 h[8]; uint4 u; } H, L;
#pragma unroll
            for (int e = 0; e < 8; ++e) {
                const float v = va[jg * 8 + e];
                H.h[e] = __float2bfloat16(v);
                L.h[e] = __float2bfloat16(v - __bfloat162float(H.h[e]));
            }
            const int gg = ahalf * 4 + jg;
            const int off = ar * 128 + ((gg ^ (ar & 7)) << 4);
            *(uint4*)(ahp + off) = H.u;
            *(uint4*)(alp + off) = L.u;
        }
    };

    auto cpB = [&](int c, int s) {
        const int r = tid & 127, lv = tid >> 7;
        const __nv_bfloat16* src =
            (lv ? Wlo : Whi) + (size_t)(n0 + r) * kD + c * 64;
        const uint32_t dst =
            smem_u32(smem + s * kSmemStage + 32768 + lv * 16384 + r * 128);
#pragma unroll
        for (int g = 0; g < 8; ++g) cp16(dst + g * 16, src + g * 8);
    };

    // --- ldmatrix lane addressing (precomputed row components) ---
    const int lidx = lane >> 3, rowoff = lane & 7;
    const int mrow = (lidx & 1) * 8 + rowoff;   // row within 16
    const int halfbit = lidx >> 1;              // k-half selector
    int rowA[4], rowB[2];
#pragma unroll
    for (int i = 0; i < 4; ++i) rowA[i] = (wm * 64 + i * 16 + mrow) * 128;
#pragma unroll
    for (int jj = 0; jj < 2; ++jj) rowB[jj] = (wn * 32 + jj * 16 + mrow) * 128;

    auto compute = [&](int s) {
        const uint32_t aB = smem_u32(smem + s * kSmemStage);
        const uint32_t bB = aB + 32768;
#pragma unroll
        for (int ks = 0; ks < 4; ++ks) {
            const int gsw = (((ks << 1) + halfbit) ^ rowoff) << 4;
            uint32_t ah[4][4], bx[2][4];
#pragma unroll
            for (int i = 0; i < 4; ++i) ldmx4(ah[i], aB + rowA[i] + gsw);
#pragma unroll
            for (int jj = 0; jj < 2; ++jj) ldmx4(bx[jj], bB + rowB[jj] + gsw);
            // term 1: Ah * Bh
#pragma unroll
            for (int i = 0; i < 4; ++i)
#pragma unroll
                for (int j = 0; j < 4; ++j)
                    mma16816(acc[i][j], ah[i], bx[j >> 1][j & 1], bx[j >> 1][2 + (j & 1)]);
            // term 2: Ah * Bl
            uint32_t bl[2][4];
#pragma unroll
            for (int jj = 0; jj < 2; ++jj) ldmx4(bl[jj], bB + 16384 + rowB[jj] + gsw);
#pragma unroll
            for (int i = 0; i < 4; ++i)
#pragma unroll
                for (int j = 0; j < 4; ++j)
                    mma16816(acc[i][j], ah[i], bl[j >> 1][j & 1], bl[j >> 1][2 + (j & 1)]);
            // term 3: Al * Bh  (reuse ah storage for Al)
#pragma unroll
            for (int i = 0; i < 4; ++i) ldmx4(ah[i], aB + 16384 + rowA[i] + gsw);
#pragma unroll
            for (int i = 0; i < 4; ++i)
#pragma unroll
                for (int j = 0; j < 4; ++j)
                    mma16816(acc[i][j], ah[i], bx[j >> 1][j & 1], bx[j >> 1][2 + (j & 1)]);
        }
    };

    // --- pipelined mainloop over 4 k-chunks ---
    ldgA(0);
    cpB(0, 0);
    CP_COMMIT();
    stsA(0);
#pragma unroll
    for (int c = 0; c < 4; ++c) {
        const int s = c & 1;
        CP_WAIT0();
        __syncthreads();
        if (c < 3) {
            ldgA(c + 1);
            cpB(c + 1, s ^ 1);
            CP_COMMIT();
        }
        compute(s);
        if (c < 3) stsA(s ^ 1);
    }

    // --- epilogue: accum -> bias add -> C ---
    const int er = lane >> 2, ec = (lane & 3) * 2;
#pragma unroll
    for (int i = 0; i < 4; ++i) {
        const int mr = m0 + wm * 64 + i * 16 + er;
#pragma unroll
        for (int j = 0; j < 4; ++j) {
            const int nc = n0 + wn * 32 + j * 8 + ec;
            const float2 b2 = *(const float2*)(bias + nc);
            float2 o0, o1;
            o0.x = acc[i][j][0] + b2.x; o0.y = acc[i][j][1] + b2.y;
            o1.x = acc[i][j][2] + b2.x; o1.y = acc[i][j][3] + b2.y;
            *(float2*)(C + (size_t)mr * kD + nc) = o0;
            *(float2*)(C + (size_t)(mr + 8) * kD + nc) = o1;
        }
    }
}

// ---------------------------------------------------------------------------
// BatchNorm stats (fp32 two-level: per-thread over 128 contiguous rows)
// ---------------------------------------------------------------------------
__global__ void stats_kernel(const float* __restrict__ X,
                             const float* __restrict__ Y,
                             float* __restrict__ s1, float* __restrict__ s2) {
    const int d = threadIdx.x;
    const size_t r0 = (size_t)blockIdx.x * 128;
    float a = 0.f, q = 0.f;
#pragma unroll 4
    for (int r = 0; r < 128; ++r) {
        float x = X[(r0 + r) * kD + d];
        if (Y) x -= Y[(r0 + r) * kD + d];
        a += x;
        q += x * x;
    }
    atomicAdd(&s1[d], a);
    atomicAdd(&s2[d], q);
}

__global__ void bn_finalize_kernel(const float* __restrict__ s1,
                                   const float* __restrict__ s2,
                                   const float* __restrict__ gamma,
                                   const float* __restrict__ beta,
                                   float* __restrict__ scale,
                                   float* __restrict__ shift) {
    const int d = threadIdx.x;
    const double mean = (double)s1[d] / (double)kN;
    const double var = (double)s2[d] / (double)kN - mean * mean;
    const float rs = (float)rsqrt(var + (double)kEps);
    const float scv = rs * gamma[d];
    scale[d] = scv;
    shift[d] = beta[d] - (float)mean * scv;
}

__global__ void zero_kernel(float* s1a, float* s2a, float* s1b, float* s2b,
                            float* se, float* wv) {
    const int g = blockIdx.x * blockDim.x + threadIdx.x;
    se[g] = 0.f;
    wv[g] = 0.f;
    if (g < kD) { s1a[g] = 0.f; s2a[g] = 0.f; s1b[g] = 0.f; s2b[g] = 0.f; }
}

// Softmax over s (logits are O(1): no max subtraction needed) + weighted V sum
__global__ void softmax_accum_kernel(const float* __restrict__ T,
                                     const float* __restrict__ V,
                                     float* __restrict__ se,
                                     float* __restrict__ wv) {
    const int b = blockIdx.x;
    const int chunk = blockIdx.y;
    const int d = threadIdx.x;
    constexpr int kChunk = kS / 16;
    float pe = 0.f, pw = 0.f;
    for (int s = chunk * kChunk; s < (chunk + 1) * kChunk; s++) {
        const size_t idx = ((size_t)s * kB + b) * kD + d;
        const float e = expf(T[idx]);
        pe += e;
        pw += e * V[idx];
    }
    atomicAdd(&se[b * kD + d], pe);
    atomicAdd(&wv[b * kD + d], pw);
}

__global__ void softmax_final_kernel(const float* __restrict__ se,
                                     const float* __restrict__ wv,
                                     float* __restrict__ concat, int head) {
    const int b = blockIdx.x;
    const int d = threadIdx.x;
    concat[b * (kH * kD) + head * kD + d] = wv[b * kD + d] / se[b * kD + d];
}

// Final MLP: [B, H*D] -> relu -> [B,D] -> relu -> [B,D] -> out
__global__ void __launch_bounds__(256)
mlp_kernel(const float* __restrict__ concat,
           const float* __restrict__ mw0, const float* __restrict__ mb0,
           const float* __restrict__ mw1, const float* __restrict__ mb1,
           const float* __restrict__ mw2, const float* __restrict__ mb2,
           float* __restrict__ out) {
    __shared__ float xs[kH * kD];
    __shared__ float h0[kD];
    __shared__ float h1[kD];
    const int b = blockIdx.x;
    const int j = threadIdx.x;

    for (int t = j; t < kH * kD; t += kD) xs[t] = concat[b * kH * kD + t];
    __syncthreads();

    float acc = mb0[j];
    for (int t = 0; t < kH * kD; t++) acc += xs[t] * mw0[(size_t)j * (kH * kD) + t];
    h0[j] = fmaxf(acc, 0.f);
    __syncthreads();

    acc = mb1[j];
    for (int t = 0; t < kD; t++) acc += h0[t] * mw1[(size_t)j * kD + t];
    h1[j] = fmaxf(acc, 0.f);
    __syncthreads();

    acc = mb2[j];
    for (int t = 0; t < kD; t++) acc += h1[t] * mw2[(size_t)j * kD + t];
    out[b * kD + j] = acc;
}

// ---------------------------------------------------------------------------
// Launcher
// ---------------------------------------------------------------------------
extern "C" void kernel_launch(void* const* d_in, const int* in_sizes, int n_in,
                              void* d_out, int out_size) {
    (void)in_sizes; (void)n_in; (void)out_size;
    const float* in_q  = (const float*)d_in[0];
    const float* in_k  = (const float*)d_in[1];
    const float* in_v  = (const float*)d_in[2];
    const float* wq    = (const float*)d_in[3];
    const float* bqv   = (const float*)d_in[4];
    const float* wk    = (const float*)d_in[5];
    const float* bkv   = (const float*)d_in[6];
    const float* wvw   = (const float*)d_in[7];
    const float* bvv   = (const float*)d_in[8];
    const float* g1    = (const float*)d_in[9];
    const float* be1   = (const float*)d_in[10];
    const float* wl1   = (const float*)d_in[11];
    const float* bl1   = (const float*)d_in[12];
    const float* g2    = (const float*)d_in[13];
    const float* be2   = (const float*)d_in[14];
    const float* wl2   = (const float*)d_in[15];
    const float* bl2   = (const float*)d_in[16];
    const float* mw0   = (const float*)d_in[17];
    const float* mb0   = (const float*)d_in[18];
    const float* mw1   = (const float*)d_in[19];
    const float* mb1   = (const float*)d_in[20];
    const float* mw2   = (const float*)d_in[21];
    const float* mb2   = (const float*)d_in[22];

    float *bq, *bk, *bv, *t2, *t4, *scA, *shA, *scB, *shB, *se, *wv, *concat;
    float *s1a, *s2a, *s1b, *s2b;
    __nv_bfloat16 *whi, *wlo;
    cudaGetSymbolAddress((void**)&bq, g_bufq);
    cudaGetSymbolAddress((void**)&bk, g_bufk);
    cudaGetSymbolAddress((void**)&bv, g_bufv);
    cudaGetSymbolAddress((void**)&t2, g_t2);
    cudaGetSymbolAddress((void**)&t4, g_t4);
    cudaGetSymbolAddress((void**)&s1a, g_s1a);
    cudaGetSymbolAddress((void**)&s2a, g_s2a);
    cudaGetSymbolAddress((void**)&s1b, g_s1b);
    cudaGetSymbolAddress((void**)&s2b, g_s2b);
    cudaGetSymbolAddress((void**)&scA, g_scA);
    cudaGetSymbolAddress((void**)&shA, g_shA);
    cudaGetSymbolAddress((void**)&scB, g_scB);
    cudaGetSymbolAddress((void**)&shB, g_shB);
    cudaGetSymbolAddress((void**)&se, g_se);
    cudaGetSymbolAddress((void**)&wv, g_wv);
    cudaGetSymbolAddress((void**)&concat, g_concat);
    cudaGetSymbolAddress((void**)&whi, g_whi);
    cudaGetSymbolAddress((void**)&wlo, g_wlo);

    cudaFuncSetAttribute(gemm_mma<0>, cudaFuncAttributeMaxDynamicSharedMemorySize, kSmemTotal);
    cudaFuncSetAttribute(gemm_mma<1>, cudaFuncAttributeMaxDynamicSharedMemorySize, kSmemTotal);
    cudaFuncSetAttribute(gemm_mma<2>, cudaFuncAttributeMaxDynamicSharedMemorySize, kSmemTotal);

    // Pre-convert all 20 weight matrices to swizzled bf16 hi/lo images.
    preconvert_w<<<dim3(20, 16), 256>>>(wq, wk, wvw, wl1, wl2);

    const size_t bufElems = (size_t)kN * kD;
    const dim3 gemmGrid(kN / 128, kD / 128);  // (512, 2)

    auto WH = [&](int slot, int head) { return whi + (size_t)(slot * 4 + head) * kD * kD; };
    auto WL = [&](int slot, int head) { return wlo + (size_t)(slot * 4 + head) * kD * kD; };

    const float *qin = in_q, *kin = in_k, *vin = in_v;
    for (int i = 0; i < kH; i++) {
        float* qout = bq + (size_t)(i & 1) * bufElems;
        float* kout = bk + (size_t)(i & 1) * bufElems;
        float* vout = bv + (size_t)(i & 1) * bufElems;

        zero_kernel<<<32, 256>>>(s1a, s2a, s1b, s2b, se, wv);

        gemm_mma<0><<<gemmGrid, 256, kSmemTotal>>>(qin, nullptr, nullptr, nullptr,
                                                   WH(0, i), WL(0, i), bqv + i * kD, qout);
        gemm_mma<0><<<gemmGrid, 256, kSmemTotal>>>(kin, nullptr, nullptr, nullptr,
                                                   WH(1, i), WL(1, i), bkv + i * kD, kout);
        gemm_mma<0><<<gemmGrid, 256, kSmemTotal>>>(vin, nullptr, nullptr, nullptr,
                                                   WH(2, i), WL(2, i), bvv + i * kD, vout);

        stats_kernel<<<512, 256>>>(kout, qout, s1a, s2a);
        bn_finalize_kernel<<<1, 256>>>(s1a, s2a, g1 + i * kD, be1 + i * kD, scA, shA);

        gemm_mma<1><<<gemmGrid, 256, kSmemTotal>>>(kout, qout, scA, shA,
                                                   WH(3, i), WL(3, i), bl1 + i * kD, t2);

        stats_kernel<<<512, 256>>>(t2, nullptr, s1b, s2b);
        bn_finalize_kernel<<<1, 256>>>(s1b, s2b, g2 + i * kD, be2 + i * kD, scB, shB);

        gemm_mma<2><<<gemmGrid, 256, kSmemTotal>>>(t2, nullptr, scB, shB,
                                                   WH(4, i), WL(4, i), bl2 + i * kD, t4);

        softmax_accum_kernel<<<dim3(kB, 16), 256>>>(t4, vout, se, wv);
        softmax_final_kernel<<<kB, 256>>>(se, wv, concat, i);

        qin = qout; kin = kout; vin = vout;
    }

    mlp_kernel<<<kB, 256>>>(concat, mw0, mb0, mw1, mb1, mw2, mb2, (float*)d_out);
}